// round 3
// baseline (speedup 1.0000x reference)
#include <cuda_runtime.h>
#include <cuda_bf16.h>

// Shapes (fixed for this problem)
//   feature_map [8,256,64,64] f32
//   x           [8,3,512,512] f32
//   W_cls       [21,256] f32
//   b_cls       [21] f32
//   out         [8,21,512,512] f32
#define B_  8
#define C_  256
#define K_  21
#define GH  64            // low-res h/w
#define GHW (GH*GH)       // 4096
#define HH  512           // high-res
#define HW_ (HH*HH)       // 262144

// ---------------- scratch (static device globals; no allocs allowed) --------
__device__ float g_seg[B_ * K_ * GHW];        // softmax(logits) at 64x64
__device__ float g_tmp[B_ * 3 * HH * GH];     // x downsampled along w
__device__ float g_xd [B_ * 3 * GHW];         // adjoint-downsampled x (T^T x)
__device__ float g_q  [B_ * K_ * 3];          // per-(b,k) color triplet

// packed fp32x2 FMA (Blackwell f32x2 pipe: 2x FFMA throughput)
__device__ __forceinline__ float2 ffma2(float2 a, float2 b, float2 c) {
    float2 d;
    asm("fma.rn.f32x2 %0, %1, %2, %3;"
        : "=l"(*reinterpret_cast<unsigned long long*>(&d))
        : "l"(*reinterpret_cast<const unsigned long long*>(&a)),
          "l"(*reinterpret_cast<const unsigned long long*>(&b)),
          "l"(*reinterpret_cast<const unsigned long long*>(&c)));
    return d;
}

// ---------------------------------------------------------------------------
// Kernel A: logits = fm . W^T + b ; seg = softmax_k(logits)   (64x64 grid)
// Block: 128 threads = 64 pixel-pairs x 2 c-halves. 256 blocks total.
// Each thread accumulates 21 packed (2-pixel) dot-products over 128 channels.
// ---------------------------------------------------------------------------
__global__ void __launch_bounds__(128) kA(const float* __restrict__ fm,
                                          const float* __restrict__ Wc,
                                          const float* __restrict__ bc) {
    __shared__ float Ws[K_ * C_];          // [k][c] row-major, 21504 B
    __shared__ float bs[K_];
    __shared__ float2 red[64][K_];         // partial sums from c-half 1

    const int tid  = threadIdx.x;
    for (int i = tid; i < K_ * C_; i += 128) Ws[i] = Wc[i];
    if (tid < K_) bs[tid] = bc[tid];
    __syncthreads();

    const int pair = tid & 63;             // 0..63
    const int ch   = tid >> 6;             // 0/1 (c-half)
    const int gp   = blockIdx.x * 128 + pair * 2;   // global pixel-pair base
    const int b    = gp >> 12;             // 4096 px per batch
    const int p    = gp & 4095;

    const float* f = fm + b * (C_ * GHW) + p;
    const int c0 = ch * 128;

    float2 acc[K_];
#pragma unroll
    for (int k = 0; k < K_; k++) acc[k] = make_float2(0.f, 0.f);

    for (int c = c0; c < c0 + 128; c += 8) {
        float2 v[8];
#pragma unroll
        for (int j = 0; j < 8; j++)
            v[j] = *reinterpret_cast<const float2*>(f + (c + j) * GHW);
#pragma unroll
        for (int k = 0; k < K_; k++) {
            const float4 w0 = *reinterpret_cast<const float4*>(&Ws[k * C_ + c]);
            const float4 w1 = *reinterpret_cast<const float4*>(&Ws[k * C_ + c + 4]);
            acc[k] = ffma2(v[0], make_float2(w0.x, w0.x), acc[k]);
            acc[k] = ffma2(v[1], make_float2(w0.y, w0.y), acc[k]);
            acc[k] = ffma2(v[2], make_float2(w0.z, w0.z), acc[k]);
            acc[k] = ffma2(v[3], make_float2(w0.w, w0.w), acc[k]);
            acc[k] = ffma2(v[4], make_float2(w1.x, w1.x), acc[k]);
            acc[k] = ffma2(v[5], make_float2(w1.y, w1.y), acc[k]);
            acc[k] = ffma2(v[6], make_float2(w1.z, w1.z), acc[k]);
            acc[k] = ffma2(v[7], make_float2(w1.w, w1.w), acc[k]);
        }
    }

    if (ch == 1) {
#pragma unroll
        for (int k = 0; k < K_; k++) red[pair][k] = acc[k];
    }
    __syncthreads();
    if (ch == 0) {
        float mx = -1e30f, my = -1e30f;
#pragma unroll
        for (int k = 0; k < K_; k++) {
            acc[k].x += red[pair][k].x + bs[k];
            acc[k].y += red[pair][k].y + bs[k];
            mx = fmaxf(mx, acc[k].x);
            my = fmaxf(my, acc[k].y);
        }
        float sx = 0.f, sy = 0.f;
#pragma unroll
        for (int k = 0; k < K_; k++) {
            acc[k].x = __expf(acc[k].x - mx);
            acc[k].y = __expf(acc[k].y - my);
            sx += acc[k].x;
            sy += acc[k].y;
        }
        const float rx = 1.f / sx, ry = 1.f / sy;
        float* so = g_seg + b * (K_ * GHW) + p;
#pragma unroll
        for (int k = 0; k < K_; k++) {
            *reinterpret_cast<float2*>(so + k * GHW) =
                make_float2(acc[k].x * rx, acc[k].y * ry);
        }
    }
}

// ---------------------------------------------------------------------------
// Kernel B1: adjoint downsample of x along w:  tmp[b,c,h,gx] = sum_w hat * x
// hat(w,g) = max(0, 1 - |w*(63/511) - g|)   (align_corners bilinear adjoint)
// Block: 256 threads = 64 gx x 4 rows; grid (128, 3, 8).
// ---------------------------------------------------------------------------
__global__ void __launch_bounds__(256) kB1(const float* __restrict__ x) {
    const int b = blockIdx.z, c = blockIdx.y;
    const int h0 = blockIdx.x * 4;
    __shared__ float rows[4][512];
    const float* src = x + ((b * 3 + c) * HH + h0) * HH;
    for (int i = threadIdx.x; i < 2048; i += 256)
        rows[i >> 9][i & 511] = src[i];
    __syncthreads();

    const int gx = threadIdx.x & 63;
    const int r  = threadIdx.x >> 6;
    const float scale = 63.0f / 511.0f;
    const int wlo = max(0, ((gx - 1) * 511) / 63);
    const int whi = min(511, ((gx + 1) * 511 + 62) / 63);
    float s = 0.f;
    for (int w = wlo; w <= whi; ++w) {
        float t = 1.0f - fabsf((float)w * scale - (float)gx);
        s += fmaxf(t, 0.f) * rows[r][w];
    }
    g_tmp[((b * 3 + c) * HH + h0 + r) * GH + gx] = s;
}

// ---------------------------------------------------------------------------
// Kernel B2: adjoint downsample along h:  xd[b,c,gy,gx] = sum_h hat * tmp
// Grid (64, 3, 8), block 64 (gx coalesced).
// ---------------------------------------------------------------------------
__global__ void __launch_bounds__(64) kB2() {
    const int b = blockIdx.z, c = blockIdx.y, gy = blockIdx.x, gx = threadIdx.x;
    const float scale = 63.0f / 511.0f;
    const int hlo = max(0, ((gy - 1) * 511) / 63);
    const int hhi = min(511, ((gy + 1) * 511 + 62) / 63);
    const float* t = g_tmp + (b * 3 + c) * (HH * GH) + gx;
    float s = 0.f;
    for (int h = hlo; h <= hhi; ++h) {
        float wt = fmaxf(1.0f - fabsf((float)h * scale - (float)gy), 0.f);
        s += wt * t[h * GH];
    }
    g_xd[((b * 3 + c) * GH + gy) * GH + gx] = s;
}

// ---------------------------------------------------------------------------
// Kernel C: q[b,k,c] = (1/HW) * <xd[b,c,:,:], seg[b,k,:,:]>
// Grid (21, 8), block 256.
// ---------------------------------------------------------------------------
__global__ void __launch_bounds__(256) kC() {
    const int k = blockIdx.x, b = blockIdx.y;
    const float* sg = g_seg + (b * K_ + k) * GHW;
    const float* X  = g_xd + b * 3 * GHW;
    float a0 = 0.f, a1 = 0.f, a2 = 0.f;
    for (int i = threadIdx.x; i < GHW; i += 256) {
        const float sv = sg[i];
        a0 += sv * X[i];
        a1 += sv * X[GHW + i];
        a2 += sv * X[2 * GHW + i];
    }
    __shared__ float red[3][256];
    red[0][threadIdx.x] = a0; red[1][threadIdx.x] = a1; red[2][threadIdx.x] = a2;
    __syncthreads();
    for (int s = 128; s > 0; s >>= 1) {
        if (threadIdx.x < s) {
            red[0][threadIdx.x] += red[0][threadIdx.x + s];
            red[1][threadIdx.x] += red[1][threadIdx.x + s];
            red[2][threadIdx.x] += red[2][threadIdx.x + s];
        }
        __syncthreads();
    }
    if (threadIdx.x == 0) {
        const float inv = 1.0f / (float)HW_;
        g_q[(b * K_ + k) * 3 + 0] = red[0][0] * inv;
        g_q[(b * K_ + k) * 3 + 1] = red[1][0] * inv;
        g_q[(b * K_ + k) * 3 + 2] = red[2][0] * inv;
    }
}

// ---------------------------------------------------------------------------
// Kernel D: out[b,k,h,w] = sum_c q[b,k,c] * x[b,c,h,w]    (DRAM-bound, 176MB)
// Grid (256, 8), block 256; float4 vectorized, x read once, 21 plane stores.
// Output is write-once/never-read: use streaming stores (__stcs) so the 176MB
// result doesn't evict x / scratch from L2.
// ---------------------------------------------------------------------------
__global__ void __launch_bounds__(256) kD(const float* __restrict__ x,
                                          float* __restrict__ out) {
    const int b = blockIdx.y;
    __shared__ float qs[K_ * 3];
    if (threadIdx.x < K_ * 3) qs[threadIdx.x] = g_q[b * K_ * 3 + threadIdx.x];
    __syncthreads();

    const int idx = blockIdx.x * 256 + threadIdx.x;   // 0..65535 float4 groups
    const float4* xb = reinterpret_cast<const float4*>(x + b * 3 * HW_);
    const float4 x0 = xb[idx];
    const float4 x1 = xb[(HW_ / 4) + idx];
    const float4 x2 = xb[(HW_ / 2) + idx];
    float4* ob = reinterpret_cast<float4*>(out + (size_t)b * K_ * HW_) + idx;

#pragma unroll
    for (int k = 0; k < K_; k++) {
        const float q0 = qs[k * 3 + 0], q1 = qs[k * 3 + 1], q2 = qs[k * 3 + 2];
        float4 o;
        o.x = q0 * x0.x + q1 * x1.x + q2 * x2.x;
        o.y = q0 * x0.y + q1 * x1.y + q2 * x2.y;
        o.z = q0 * x0.z + q1 * x1.z + q2 * x2.z;
        o.w = q0 * x0.w + q1 * x1.w + q2 * x2.w;
        __stcs(ob + k * (HW_ / 4), o);
    }
}

// ---------------------------------------------------------------------------
extern "C" void kernel_launch(void* const* d_in, const int* in_sizes, int n_in,
                              void* d_out, int out_size) {
    const float* fm  = (const float*)d_in[0];   // [8,256,64,64]
    const float* x   = (const float*)d_in[1];   // [8,3,512,512]
    const float* Wc  = (const float*)d_in[2];   // [21,256]
    const float* bc  = (const float*)d_in[3];   // [21]
    float* out = (float*)d_out;                 // [8,21,512,512]

    kA<<<256, 128>>>(fm, Wc, bc);
    kB1<<<dim3(128, 3, B_), 256>>>(x);
    kB2<<<dim3(GH, 3, B_), 64>>>();
    kC<<<dim3(K_, B_), 256>>>();
    kD<<<dim3(256, B_), 256>>>(x, out);
}

// round 11
// speedup vs baseline: 1.0472x; 1.0472x over previous
#include <cuda_runtime.h>
#include <cuda_bf16.h>

// Shapes (fixed for this problem)
//   feature_map [8,256,64,64] f32
//   x           [8,3,512,512] f32
//   W_cls       [21,256] f32
//   b_cls       [21] f32
//   out         [8,21,512,512] f32
#define B_  8
#define C_  256
#define K_  21
#define GH  64            // low-res h/w
#define GHW (GH*GH)       // 4096
#define HH  512           // high-res
#define HW_ (HH*HH)       // 262144

// ---------------- scratch (static device globals; no allocs allowed) --------
__device__ float g_seg[B_ * K_ * GHW];        // softmax(logits) at 64x64
__device__ float g_tmp[B_ * 3 * HH * GH];     // x downsampled along w
__device__ float g_xd [B_ * 3 * GHW];         // adjoint-downsampled x (T^T x)
__device__ float g_q  [B_ * K_ * 3];          // per-(b,k) color triplet

// packed fp32x2 FMA (Blackwell f32x2 pipe: 2x FFMA throughput)
__device__ __forceinline__ float2 ffma2(float2 a, float2 b, float2 c) {
    float2 d;
    asm("fma.rn.f32x2 %0, %1, %2, %3;"
        : "=l"(*reinterpret_cast<unsigned long long*>(&d))
        : "l"(*reinterpret_cast<const unsigned long long*>(&a)),
          "l"(*reinterpret_cast<const unsigned long long*>(&b)),
          "l"(*reinterpret_cast<const unsigned long long*>(&c)));
    return d;
}

// ---------------------------------------------------------------------------
// Kernel A: logits = fm . W^T + b ; seg = softmax_k(logits)   (64x64 grid)
// Block: 128 threads = 64 pixel-pairs x 2 c-halves. 256 blocks total.
// ---------------------------------------------------------------------------
__global__ void __launch_bounds__(128) kA(const float* __restrict__ fm,
                                          const float* __restrict__ Wc,
                                          const float* __restrict__ bc) {
    __shared__ float Ws[K_ * C_];          // [k][c] row-major, 21504 B
    __shared__ float bs[K_];
    __shared__ float2 red[64][K_];         // partial sums from c-half 1

    const int tid  = threadIdx.x;
    for (int i = tid; i < K_ * C_; i += 128) Ws[i] = Wc[i];
    if (tid < K_) bs[tid] = bc[tid];
    __syncthreads();

    const int pair = tid & 63;             // 0..63
    const int ch   = tid >> 6;             // 0/1 (c-half)
    const int gp   = blockIdx.x * 128 + pair * 2;   // global pixel-pair base
    const int b    = gp >> 12;             // 4096 px per batch
    const int p    = gp & 4095;

    const float* f = fm + b * (C_ * GHW) + p;
    const int c0 = ch * 128;

    float2 acc[K_];
#pragma unroll
    for (int k = 0; k < K_; k++) acc[k] = make_float2(0.f, 0.f);

    for (int c = c0; c < c0 + 128; c += 8) {
        float2 v[8];
#pragma unroll
        for (int j = 0; j < 8; j++)
            v[j] = *reinterpret_cast<const float2*>(f + (c + j) * GHW);
#pragma unroll
        for (int k = 0; k < K_; k++) {
            const float4 w0 = *reinterpret_cast<const float4*>(&Ws[k * C_ + c]);
            const float4 w1 = *reinterpret_cast<const float4*>(&Ws[k * C_ + c + 4]);
            acc[k] = ffma2(v[0], make_float2(w0.x, w0.x), acc[k]);
            acc[k] = ffma2(v[1], make_float2(w0.y, w0.y), acc[k]);
            acc[k] = ffma2(v[2], make_float2(w0.z, w0.z), acc[k]);
            acc[k] = ffma2(v[3], make_float2(w0.w, w0.w), acc[k]);
            acc[k] = ffma2(v[4], make_float2(w1.x, w1.x), acc[k]);
            acc[k] = ffma2(v[5], make_float2(w1.y, w1.y), acc[k]);
            acc[k] = ffma2(v[6], make_float2(w1.z, w1.z), acc[k]);
            acc[k] = ffma2(v[7], make_float2(w1.w, w1.w), acc[k]);
        }
    }

    if (ch == 1) {
#pragma unroll
        for (int k = 0; k < K_; k++) red[pair][k] = acc[k];
    }
    __syncthreads();
    if (ch == 0) {
        float mx = -1e30f, my = -1e30f;
#pragma unroll
        for (int k = 0; k < K_; k++) {
            acc[k].x += red[pair][k].x + bs[k];
            acc[k].y += red[pair][k].y + bs[k];
            mx = fmaxf(mx, acc[k].x);
            my = fmaxf(my, acc[k].y);
        }
        float sx = 0.f, sy = 0.f;
#pragma unroll
        for (int k = 0; k < K_; k++) {
            acc[k].x = __expf(acc[k].x - mx);
            acc[k].y = __expf(acc[k].y - my);
            sx += acc[k].x;
            sy += acc[k].y;
        }
        const float rx = 1.f / sx, ry = 1.f / sy;
        float* so = g_seg + b * (K_ * GHW) + p;
#pragma unroll
        for (int k = 0; k < K_; k++) {
            *reinterpret_cast<float2*>(so + k * GHW) =
                make_float2(acc[k].x * rx, acc[k].y * ry);
        }
    }
}

// ---------------------------------------------------------------------------
// Kernel B1: adjoint downsample of x along w:  tmp[b,c,h,gx] = sum_w hat * x
// hat(w,g) = max(0, 1 - |w*(63/511) - g|)   (align_corners bilinear adjoint)
// ---------------------------------------------------------------------------
__global__ void __launch_bounds__(256) kB1(const float* __restrict__ x) {
    const int b = blockIdx.z, c = blockIdx.y;
    const int h0 = blockIdx.x * 4;
    __shared__ float rows[4][512];
    const float* src = x + ((b * 3 + c) * HH + h0) * HH;
    for (int i = threadIdx.x; i < 2048; i += 256)
        rows[i >> 9][i & 511] = src[i];
    __syncthreads();

    const int gx = threadIdx.x & 63;
    const int r  = threadIdx.x >> 6;
    const float scale = 63.0f / 511.0f;
    const int wlo = max(0, ((gx - 1) * 511) / 63);
    const int whi = min(511, ((gx + 1) * 511 + 62) / 63);
    float s = 0.f;
    for (int w = wlo; w <= whi; ++w) {
        float t = 1.0f - fabsf((float)w * scale - (float)gx);
        s += fmaxf(t, 0.f) * rows[r][w];
    }
    g_tmp[((b * 3 + c) * HH + h0 + r) * GH + gx] = s;
}

// ---------------------------------------------------------------------------
// Kernel B2: adjoint downsample along h:  xd[b,c,gy,gx] = sum_h hat * tmp
// ---------------------------------------------------------------------------
__global__ void __launch_bounds__(64) kB2() {
    const int b = blockIdx.z, c = blockIdx.y, gy = blockIdx.x, gx = threadIdx.x;
    const float scale = 63.0f / 511.0f;
    const int hlo = max(0, ((gy - 1) * 511) / 63);
    const int hhi = min(511, ((gy + 1) * 511 + 62) / 63);
    const float* t = g_tmp + (b * 3 + c) * (HH * GH) + gx;
    float s = 0.f;
    for (int h = hlo; h <= hhi; ++h) {
        float wt = fmaxf(1.0f - fabsf((float)h * scale - (float)gy), 0.f);
        s += wt * t[h * GH];
    }
    g_xd[((b * 3 + c) * GH + gy) * GH + gx] = s;
}

// ---------------------------------------------------------------------------
// Kernel C: q[b,k,c] = (1/HW) * <xd[b,c,:,:], seg[b,k,:,:]>
// Grid (21, 8), block 256. float4 loads (4 iters/thread), warp-shuffle
// reduction (no barrier), one __syncthreads, 8-lane shuffle finish.
// Old version was 13.7us of pure barrier/latency overhead.
// ---------------------------------------------------------------------------
__global__ void __launch_bounds__(256) kC() {
    const int k = blockIdx.x, b = blockIdx.y;
    const float4* sg = reinterpret_cast<const float4*>(g_seg + (b * K_ + k) * GHW);
    const float4* X0 = reinterpret_cast<const float4*>(g_xd + b * 3 * GHW);
    const float4* X1 = X0 + GHW / 4;
    const float4* X2 = X1 + GHW / 4;

    float a0 = 0.f, a1 = 0.f, a2 = 0.f;
#pragma unroll
    for (int it = 0; it < 4; ++it) {
        const int i = threadIdx.x + it * 256;     // GHW/4 = 1024 float4s
        const float4 s4 = sg[i];
        const float4 v0 = X0[i];
        const float4 v1 = X1[i];
        const float4 v2 = X2[i];
        a0 += s4.x * v0.x + s4.y * v0.y + s4.z * v0.z + s4.w * v0.w;
        a1 += s4.x * v1.x + s4.y * v1.y + s4.z * v1.z + s4.w * v1.w;
        a2 += s4.x * v2.x + s4.y * v2.y + s4.z * v2.z + s4.w * v2.w;
    }

#pragma unroll
    for (int off = 16; off > 0; off >>= 1) {
        a0 += __shfl_xor_sync(0xffffffffu, a0, off);
        a1 += __shfl_xor_sync(0xffffffffu, a1, off);
        a2 += __shfl_xor_sync(0xffffffffu, a2, off);
    }

    __shared__ float ws[3][8];
    const int warp = threadIdx.x >> 5;
    if ((threadIdx.x & 31) == 0) {
        ws[0][warp] = a0; ws[1][warp] = a1; ws[2][warp] = a2;
    }
    __syncthreads();
    if (threadIdx.x < 8) {
        float r0 = ws[0][threadIdx.x];
        float r1 = ws[1][threadIdx.x];
        float r2 = ws[2][threadIdx.x];
#pragma unroll
        for (int off = 4; off > 0; off >>= 1) {
            r0 += __shfl_xor_sync(0x000000ffu, r0, off);
            r1 += __shfl_xor_sync(0x000000ffu, r1, off);
            r2 += __shfl_xor_sync(0x000000ffu, r2, off);
        }
        if (threadIdx.x == 0) {
            const float inv = 1.0f / (float)HW_;
            g_q[(b * K_ + k) * 3 + 0] = r0 * inv;
            g_q[(b * K_ + k) * 3 + 1] = r1 * inv;
            g_q[(b * K_ + k) * 3 + 2] = r2 * inv;
        }
    }
}

// ---------------------------------------------------------------------------
// Kernel D: out[b,k,h,w] = sum_c q[b,k,c] * x[b,c,h,w]    (DRAM-bound, 176MB)
// Output is write-once/never-read: streaming stores (__stcs) avoid polluting
// L2 and any write-allocate overhead.
// ---------------------------------------------------------------------------
__global__ void __launch_bounds__(256) kD(const float* __restrict__ x,
                                          float* __restrict__ out) {
    const int b = blockIdx.y;
    __shared__ float qs[K_ * 3];
    if (threadIdx.x < K_ * 3) qs[threadIdx.x] = g_q[b * K_ * 3 + threadIdx.x];
    __syncthreads();

    const int idx = blockIdx.x * 256 + threadIdx.x;   // 0..65535 float4 groups
    const float4* xb = reinterpret_cast<const float4*>(x + b * 3 * HW_);
    const float4 x0 = xb[idx];
    const float4 x1 = xb[(HW_ / 4) + idx];
    const float4 x2 = xb[(HW_ / 2) + idx];
    float4* ob = reinterpret_cast<float4*>(out + (size_t)b * K_ * HW_) + idx;

#pragma unroll
    for (int k = 0; k < K_; k++) {
        const float q0 = qs[k * 3 + 0], q1 = qs[k * 3 + 1], q2 = qs[k * 3 + 2];
        float4 o;
        o.x = q0 * x0.x + q1 * x1.x + q2 * x2.x;
        o.y = q0 * x0.y + q1 * x1.y + q2 * x2.y;
        o.z = q0 * x0.z + q1 * x1.z + q2 * x2.z;
        o.w = q0 * x0.w + q1 * x1.w + q2 * x2.w;
        __stcs(ob + k * (HW_ / 4), o);
    }
}

// ---------------------------------------------------------------------------
extern "C" void kernel_launch(void* const* d_in, const int* in_sizes, int n_in,
                              void* d_out, int out_size) {
    const float* fm  = (const float*)d_in[0];   // [8,256,64,64]
    const float* x   = (const float*)d_in[1];   // [8,3,512,512]
    const float* Wc  = (const float*)d_in[2];   // [21,256]
    const float* bc  = (const float*)d_in[3];   // [21]
    float* out = (float*)d_out;                 // [8,21,512,512]

    kA<<<256, 128>>>(fm, Wc, bc);
    kB1<<<dim3(128, 3, B_), 256>>>(x);
    kB2<<<dim3(GH, 3, B_), 64>>>();
    kC<<<dim3(K_, B_), 256>>>();
    kD<<<dim3(256, B_), 256>>>(x, out);
}